// round 2
// baseline (speedup 1.0000x reference)
#include <cuda_runtime.h>
#include <math.h>

#define BB 4
#define TT 512
#define SS 1536           // S = 3*T
#define SDIM 64
#define ADIM 32
#define HDIM 512
#define NH 8
#define DH 64
#define NBLK 6
#define DFF 2048
#define MROWS (BB*SS)     // 6144

enum { EP_BIAS = 0, EP_BIAS_RES = 1, EP_BIAS_GELU = 2 };

// ---------------- scratch (static device globals; no runtime allocs) ----------
__device__ float g_h   [MROWS * HDIM];
__device__ float g_q   [MROWS * HDIM];
__device__ float g_k   [MROWS * HDIM];
__device__ float g_v   [MROWS * HDIM];
__device__ float g_ctx [MROWS * HDIM];
__device__ float g_xa  [MROWS * HDIM];
__device__ float g_ln1 [MROWS * HDIM];
__device__ float g_pre2[MROWS * HDIM];
__device__ float g_mlp [MROWS * DFF];
__device__ float g_sc  [(size_t)BB * NH * SS * SS];   // 302 MB scores

// ---------------- tf32 mma helpers ----------------
__device__ __forceinline__ unsigned f2tf(float x) {
    unsigned r; asm("cvt.rna.tf32.f32 %0, %1;" : "=r"(r) : "f"(x)); return r;
}
__device__ __forceinline__ void mma8(float c[4],
    unsigned a0, unsigned a1, unsigned a2, unsigned a3,
    unsigned b0, unsigned b1)
{
    asm volatile(
      "mma.sync.aligned.m16n8k8.row.col.f32.tf32.tf32.f32 "
      "{%0,%1,%2,%3},{%4,%5,%6,%7},{%8,%9},{%0,%1,%2,%3};"
      : "+f"(c[0]), "+f"(c[1]), "+f"(c[2]), "+f"(c[3])
      : "r"(a0), "r"(a1), "r"(a2), "r"(a3), "r"(b0), "r"(b1));
}

// ---------------- reductions ----------------
__device__ __forceinline__ float blockReduceSum(float v, float* sm) {
    int lane = threadIdx.x & 31, wid = threadIdx.x >> 5;
    #pragma unroll
    for (int o = 16; o; o >>= 1) v += __shfl_down_sync(0xffffffffu, v, o);
    if (lane == 0) sm[wid] = v;
    __syncthreads();
    float r = 0.f;
    if (wid == 0) {
        r = (lane < 8) ? sm[lane] : 0.f;
        #pragma unroll
        for (int o = 4; o; o >>= 1) r += __shfl_down_sync(0xffffffffu, r, o);
        if (lane == 0) sm[0] = r;
    }
    __syncthreads();
    r = sm[0];
    __syncthreads();
    return r;
}

__device__ __forceinline__ float blockReduceMax(float v, float* sm) {
    int lane = threadIdx.x & 31, wid = threadIdx.x >> 5;
    #pragma unroll
    for (int o = 16; o; o >>= 1) v = fmaxf(v, __shfl_down_sync(0xffffffffu, v, o));
    if (lane == 0) sm[wid] = v;
    __syncthreads();
    float r = -1e30f;
    if (wid == 0) {
        r = (lane < 8) ? sm[lane] : -1e30f;
        #pragma unroll
        for (int o = 4; o; o >>= 1) r = fmaxf(r, __shfl_down_sync(0xffffffffu, r, o));
        if (lane == 0) sm[0] = r;
    }
    __syncthreads();
    r = sm[0];
    __syncthreads();
    return r;
}

// ---------------- embedding + eLN (one block per sequence row) ----------------
__global__ __launch_bounds__(256) void embed_kernel(
    const int* __restrict__ timesteps, const float* __restrict__ s0,
    const float* __restrict__ s1, const float* __restrict__ act,
    const float* __restrict__ temb,
    const float* __restrict__ Ws, const float* __restrict__ bs,
    const float* __restrict__ Wa, const float* __restrict__ ba,
    const float* __restrict__ eg, const float* __restrict__ eb,
    float* __restrict__ out)
{
    int s = blockIdx.x;
    int b = s / SS, sr = s % SS;
    int t = sr / 3, r = sr % 3;

    __shared__ float sIn[SDIM];
    __shared__ float red[32];

    const float* inp; const float* W; const float* bias; int Kin;
    if (r == 0)      { inp = s0  + (size_t)(b*TT + t)*SDIM; W = Ws; bias = bs; Kin = SDIM; }
    else if (r == 1) { inp = s1  + (size_t)(b*TT + t)*SDIM; W = Ws; bias = bs; Kin = SDIM; }
    else             { inp = act + (size_t)(b*TT + t)*ADIM; W = Wa; bias = ba; Kin = ADIM; }

    int tid = threadIdx.x;
    if (tid < Kin) sIn[tid] = inp[tid];
    __syncthreads();

    int tsv = timesteps[b*TT + t];
    const float* te = temb + (size_t)tsv * HDIM;

    float v0, v1;
    {
        int c = tid;
        float a = bias[c] + te[c];
        for (int k = 0; k < Kin; k++) a = fmaf(sIn[k], W[(size_t)k*HDIM + c], a);
        v0 = a;
        c = tid + 256;
        a = bias[c] + te[c];
        for (int k = 0; k < Kin; k++) a = fmaf(sIn[k], W[(size_t)k*HDIM + c], a);
        v1 = a;
    }
    float sum = blockReduceSum(v0 + v1, red);
    float m = sum * (1.0f / HDIM);
    float d0 = v0 - m, d1 = v1 - m;
    float ssq = blockReduceSum(d0*d0 + d1*d1, red);
    float rstd = rsqrtf(ssq * (1.0f / HDIM) + 1e-5f);
    out[(size_t)s*HDIM + tid      ] = d0 * rstd * eg[tid]       + eb[tid];
    out[(size_t)s*HDIM + tid + 256] = d1 * rstd * eg[tid + 256] + eb[tid + 256];
}

// ============ tensor-core GEMM body: C[M,N] = A[M,K] @ B[K,N] (3xTF32) =========
// 256 threads, tile 128x128, BK=16. Warp grid 2(m) x 4(n): warp tile 64x32.
__device__ __forceinline__ void tgemm_body(
    const float* __restrict__ A, const float* __restrict__ B,
    const float* __restrict__ bias, const float* __restrict__ res,
    float* __restrict__ C, int M, int N, int K, int ep)
{
    __shared__ float As[16][136];
    __shared__ float Bs[16][136];
    const int tid  = threadIdx.x, lane = tid & 31, warp = tid >> 5;
    const int g    = lane >> 2,  tg   = lane & 3;
    const int wm0  = (warp >> 2) * 64, wn0 = (warp & 3) * 32;
    const int m0   = blockIdx.y * 128, n0 = blockIdx.x * 128;
    const int ar   = tid >> 2,  ac = (tid & 3) * 4;
    const int brr  = tid >> 5,  bcc = (tid & 31) * 4;

    float acc[4][4][4];
    #pragma unroll
    for (int i = 0; i < 4; i++)
        #pragma unroll
        for (int j = 0; j < 4; j++)
            #pragma unroll
            for (int l = 0; l < 4; l++) acc[i][j][l] = 0.f;

    for (int k0 = 0; k0 < K; k0 += 16) {
        float4 av0 = *(const float4*)(A + (size_t)(m0 + ar)*K      + k0 + ac);
        float4 av1 = *(const float4*)(A + (size_t)(m0 + ar + 64)*K + k0 + ac);
        float4 bv0 = *(const float4*)(B + (size_t)(k0 + brr)*N     + n0 + bcc);
        float4 bv1 = *(const float4*)(B + (size_t)(k0 + brr + 8)*N + n0 + bcc);
        As[ac+0][ar] = av0.x; As[ac+1][ar] = av0.y; As[ac+2][ar] = av0.z; As[ac+3][ar] = av0.w;
        As[ac+0][ar+64] = av1.x; As[ac+1][ar+64] = av1.y; As[ac+2][ar+64] = av1.z; As[ac+3][ar+64] = av1.w;
        *(float4*)&Bs[brr][bcc]   = bv0;
        *(float4*)&Bs[brr+8][bcc] = bv1;
        __syncthreads();
        #pragma unroll
        for (int ks = 0; ks < 16; ks += 8) {
            unsigned ah[4][4], al[4][4], bh[4][2], bl[4][2];
            #pragma unroll
            for (int tm = 0; tm < 4; tm++) {
                int m = wm0 + tm*16 + g;
                float f0 = As[ks+tg][m],   f1 = As[ks+tg][m+8];
                float f2 = As[ks+tg+4][m], f3 = As[ks+tg+4][m+8];
                ah[tm][0] = f2tf(f0); al[tm][0] = f2tf(f0 - __uint_as_float(ah[tm][0]));
                ah[tm][1] = f2tf(f1); al[tm][1] = f2tf(f1 - __uint_as_float(ah[tm][1]));
                ah[tm][2] = f2tf(f2); al[tm][2] = f2tf(f2 - __uint_as_float(ah[tm][2]));
                ah[tm][3] = f2tf(f3); al[tm][3] = f2tf(f3 - __uint_as_float(ah[tm][3]));
            }
            #pragma unroll
            for (int tn = 0; tn < 4; tn++) {
                int n = wn0 + tn*8 + g;
                float f0 = Bs[ks+tg][n], f1 = Bs[ks+tg+4][n];
                bh[tn][0] = f2tf(f0); bl[tn][0] = f2tf(f0 - __uint_as_float(bh[tn][0]));
                bh[tn][1] = f2tf(f1); bl[tn][1] = f2tf(f1 - __uint_as_float(bh[tn][1]));
            }
            #pragma unroll
            for (int tm = 0; tm < 4; tm++)
                #pragma unroll
                for (int tn = 0; tn < 4; tn++) {
                    mma8(acc[tm][tn], ah[tm][0],ah[tm][1],ah[tm][2],ah[tm][3], bh[tn][0],bh[tn][1]);
                    mma8(acc[tm][tn], al[tm][0],al[tm][1],al[tm][2],al[tm][3], bh[tn][0],bh[tn][1]);
                    mma8(acc[tm][tn], ah[tm][0],ah[tm][1],ah[tm][2],ah[tm][3], bl[tn][0],bl[tn][1]);
                }
        }
        __syncthreads();
    }
    #pragma unroll
    for (int tm = 0; tm < 4; tm++) {
        #pragma unroll
        for (int tn = 0; tn < 4; tn++) {
            int row = m0 + wm0 + tm*16 + g;
            int col = n0 + wn0 + tn*8 + tg*2;
            float b0v = bias[col], b1v = bias[col+1];
            float v00 = acc[tm][tn][0] + b0v, v01 = acc[tm][tn][1] + b1v;
            float v10 = acc[tm][tn][2] + b0v, v11 = acc[tm][tn][3] + b1v;
            if (ep == EP_BIAS_RES) {
                v00 += res[(size_t)row*N + col];     v01 += res[(size_t)row*N + col + 1];
                v10 += res[(size_t)(row+8)*N + col]; v11 += res[(size_t)(row+8)*N + col + 1];
            } else if (ep == EP_BIAS_GELU) {
                v00 = 0.5f*v00*(1.0f + erff(v00*0.70710678118654752f));
                v01 = 0.5f*v01*(1.0f + erff(v01*0.70710678118654752f));
                v10 = 0.5f*v10*(1.0f + erff(v10*0.70710678118654752f));
                v11 = 0.5f*v11*(1.0f + erff(v11*0.70710678118654752f));
            }
            *(float2*)(C + (size_t)row*N + col)     = make_float2(v00, v01);
            *(float2*)(C + (size_t)(row+8)*N + col) = make_float2(v10, v11);
        }
    }
}

__global__ __launch_bounds__(256) void tgemm_kernel(
    const float* __restrict__ A, const float* __restrict__ B,
    const float* __restrict__ bias, const float* __restrict__ res,
    float* __restrict__ C, int M, int N, int K, int ep)
{
    tgemm_body(A, B, bias, res, C, M, N, K, ep);
}

// fused QKV: blockIdx.z selects the projection
__global__ __launch_bounds__(256) void qkv_kernel(
    const float* __restrict__ h,
    const float* __restrict__ Wq, const float* __restrict__ Wk, const float* __restrict__ Wv,
    const float* __restrict__ bq, const float* __restrict__ bk, const float* __restrict__ bv,
    float* __restrict__ q, float* __restrict__ k, float* __restrict__ v)
{
    const float* W; const float* bias; float* out;
    if      (blockIdx.z == 0) { W = Wq; bias = bq; out = q; }
    else if (blockIdx.z == 1) { W = Wk; bias = bk; out = k; }
    else                      { W = Wv; bias = bv; out = v; }
    tgemm_body(h, W, bias, nullptr, out, MROWS, HDIM, HDIM, EP_BIAS);
}

// ---------- scores = Q @ K^T (NT), lower-triangle 128x128 tiles, 3xTF32 -------
__global__ __launch_bounds__(256) void tscores_kernel(
    const float* __restrict__ q, const float* __restrict__ k, float* __restrict__ sc)
{
    int jt = blockIdx.x, it = blockIdx.y;
    if (jt > it) return;
    int bh = blockIdx.z, b = bh >> 3, h = bh & 7;
    const float* qb = q + (size_t)b*SS*HDIM + h*DH;
    const float* kb = k + (size_t)b*SS*HDIM + h*DH;
    float* cb = sc + (size_t)bh * SS * SS;
    int i0 = it * 128, j0 = jt * 128;

    __shared__ float Qs[16][136];
    __shared__ float Ks[128][20];
    const int tid  = threadIdx.x, lane = tid & 31, warp = tid >> 5;
    const int g    = lane >> 2,  tg   = lane & 3;
    const int wm0  = (warp >> 2) * 64, wn0 = (warp & 3) * 32;
    const int ar   = tid >> 2,  ac = (tid & 3) * 4;

    float acc[4][4][4];
    #pragma unroll
    for (int i = 0; i < 4; i++)
        #pragma unroll
        for (int j = 0; j < 4; j++)
            #pragma unroll
            for (int l = 0; l < 4; l++) acc[i][j][l] = 0.f;

    for (int k0 = 0; k0 < DH; k0 += 16) {
        float4 q0 = *(const float4*)(qb + (size_t)(i0 + ar)*HDIM      + k0 + ac);
        float4 q1 = *(const float4*)(qb + (size_t)(i0 + ar + 64)*HDIM + k0 + ac);
        float4 k0v = *(const float4*)(kb + (size_t)(j0 + ar)*HDIM      + k0 + ac);
        float4 k1v = *(const float4*)(kb + (size_t)(j0 + ar + 64)*HDIM + k0 + ac);
        Qs[ac+0][ar] = q0.x; Qs[ac+1][ar] = q0.y; Qs[ac+2][ar] = q0.z; Qs[ac+3][ar] = q0.w;
        Qs[ac+0][ar+64] = q1.x; Qs[ac+1][ar+64] = q1.y; Qs[ac+2][ar+64] = q1.z; Qs[ac+3][ar+64] = q1.w;
        *(float4*)&Ks[ar][ac]    = k0v;
        *(float4*)&Ks[ar+64][ac] = k1v;
        __syncthreads();
        #pragma unroll
        for (int ks = 0; ks < 16; ks += 8) {
            unsigned ah[4][4], al[4][4], bh[4][2], bl[4][2];
            #pragma unroll
            for (int tm = 0; tm < 4; tm++) {
                int m = wm0 + tm*16 + g;
                float f0 = Qs[ks+tg][m],   f1 = Qs[ks+tg][m+8];
                float f2 = Qs[ks+tg+4][m], f3 = Qs[ks+tg+4][m+8];
                ah[tm][0] = f2tf(f0); al[tm][0] = f2tf(f0 - __uint_as_float(ah[tm][0]));
                ah[tm][1] = f2tf(f1); al[tm][1] = f2tf(f1 - __uint_as_float(ah[tm][1]));
                ah[tm][2] = f2tf(f2); al[tm][2] = f2tf(f2 - __uint_as_float(ah[tm][2]));
                ah[tm][3] = f2tf(f3); al[tm][3] = f2tf(f3 - __uint_as_float(ah[tm][3]));
            }
            #pragma unroll
            for (int tn = 0; tn < 4; tn++) {
                int n = wn0 + tn*8 + g;
                float f0 = Ks[n][ks+tg], f1 = Ks[n][ks+tg+4];
                bh[tn][0] = f2tf(f0); bl[tn][0] = f2tf(f0 - __uint_as_float(bh[tn][0]));
                bh[tn][1] = f2tf(f1); bl[tn][1] = f2tf(f1 - __uint_as_float(bh[tn][1]));
            }
            #pragma unroll
            for (int tm = 0; tm < 4; tm++)
                #pragma unroll
                for (int tn = 0; tn < 4; tn++) {
                    mma8(acc[tm][tn], ah[tm][0],ah[tm][1],ah[tm][2],ah[tm][3], bh[tn][0],bh[tn][1]);
                    mma8(acc[tm][tn], al[tm][0],al[tm][1],al[tm][2],al[tm][3], bh[tn][0],bh[tn][1]);
                    mma8(acc[tm][tn], ah[tm][0],ah[tm][1],ah[tm][2],ah[tm][3], bl[tn][0],bl[tn][1]);
                }
        }
        __syncthreads();
    }
    const float scale = 0.125f;
    #pragma unroll
    for (int tm = 0; tm < 4; tm++)
        #pragma unroll
        for (int tn = 0; tn < 4; tn++) {
            int row = i0 + wm0 + tm*16 + g;
            int col = j0 + wn0 + tn*8 + tg*2;
            *(float2*)(cb + (size_t)row*SS + col) =
                make_float2(acc[tm][tn][0]*scale, acc[tm][tn][1]*scale);
            *(float2*)(cb + (size_t)(row+8)*SS + col) =
                make_float2(acc[tm][tn][2]*scale, acc[tm][tn][3]*scale);
        }
}

// ---------------- causal row softmax, single read + single write --------------
__global__ __launch_bounds__(256) void softmax_kernel(float* __restrict__ sc)
{
    size_t rid = blockIdx.x;            // bh*S + i
    int i = (int)(rid % SS);
    float* row = sc + rid * (size_t)SS;
    int n = i + 1;
    int end = ((i >> 7) + 1) << 7;      // 128-tile boundary for ctx GEMM
    __shared__ float red[32];

    float vals[6];
    int cnt = 0;
    float mx = -1e30f;
    for (int j = threadIdx.x; j < n; j += 256) {
        float x = row[j];
        vals[cnt++] = x;
        mx = fmaxf(mx, x);
    }
    mx = blockReduceMax(mx, red);

    float sum = 0.f;
    #pragma unroll
    for (int l = 0; l < 6; l++)
        if (l < cnt) { float e = __expf(vals[l] - mx); vals[l] = e; sum += e; }
    sum = blockReduceSum(sum, red);
    float inv = 1.0f / sum;

    cnt = 0;
    for (int j = threadIdx.x; j < n; j += 256) row[j] = vals[cnt++] * inv;
    for (int j = n + threadIdx.x; j < end; j += 256) row[j] = 0.f;
}

// ---------- ctx = attn @ V (NN), tile 128x64, causal K-limit, 3xTF32 ----------
__global__ __launch_bounds__(256) void tctx_kernel(
    const float* __restrict__ at, const float* __restrict__ v, float* __restrict__ ctx)
{
    int it = blockIdx.x, bh = blockIdx.y, b = bh >> 3, h = bh & 7;
    const float* ab = at + (size_t)bh * SS * SS;
    const float* vb = v   + (size_t)b*SS*HDIM + h*DH;
    float* cb       = ctx + (size_t)b*SS*HDIM + h*DH;
    int i0 = it * 128;
    int kmax = (it + 1) * 128;

    __shared__ float As[16][136];
    __shared__ float Bs[16][72];
    const int tid  = threadIdx.x, lane = tid & 31, warp = tid >> 5;
    const int g    = lane >> 2,  tg   = lane & 3;
    const int wm0  = (warp >> 1) * 32, wn0 = (warp & 1) * 32;
    const int ar   = tid >> 2,  ac = (tid & 3) * 4;
    const int brr  = tid >> 4,  bcc = (tid & 15) * 4;

    float acc[2][4][4];
    #pragma unroll
    for (int i = 0; i < 2; i++)
        #pragma unroll
        for (int j = 0; j < 4; j++)
            #pragma unroll
            for (int l = 0; l < 4; l++) acc[i][j][l] = 0.f;

    for (int k0 = 0; k0 < kmax; k0 += 16) {
        float4 a0 = *(const float4*)(ab + (size_t)(i0 + ar)*SS      + k0 + ac);
        float4 a1 = *(const float4*)(ab + (size_t)(i0 + ar + 64)*SS + k0 + ac);
        float4 b0 = *(const float4*)(vb + (size_t)(k0 + brr)*HDIM + bcc);
        As[ac+0][ar] = a0.x; As[ac+1][ar] = a0.y; As[ac+2][ar] = a0.z; As[ac+3][ar] = a0.w;
        As[ac+0][ar+64] = a1.x; As[ac+1][ar+64] = a1.y; As[ac+2][ar+64] = a1.z; As[ac+3][ar+64] = a1.w;
        *(float4*)&Bs[brr][bcc] = b0;
        __syncthreads();
        #pragma unroll
        for (int ks = 0; ks < 16; ks += 8) {
            unsigned ah[2][4], al[2][4], bh[4][2], bl[4][2];
            #pragma unroll
            for (int tm = 0; tm < 2; tm++) {
                int m = wm0 + tm*16 + g;
                float f0 = As[ks+tg][m],   f1 = As[ks+tg][m+8];
                float f2 = As[ks+tg+4][m], f3 = As[ks+tg+4][m+8];
                ah[tm][0] = f2tf(f0); al[tm][0] = f2tf(f0 - __uint_as_float(ah[tm][0]));
                ah[tm][1] = f2tf(f1); al[tm][1] = f2tf(f1 - __uint_as_float(ah[tm][1]));
                ah[tm][2] = f2tf(f2); al[tm][2] = f2tf(f2 - __uint_as_float(ah[tm][2]));
                ah[tm][3] = f2tf(f3); al[tm][3] = f2tf(f3 - __uint_as_float(ah[tm][3]));
            }
            #pragma unroll
            for (int tn = 0; tn < 4; tn++) {
                int n = wn0 + tn*8 + g;
                float f0 = Bs[ks+tg][n], f1 = Bs[ks+tg+4][n];
                bh[tn][0] = f2tf(f0); bl[tn][0] = f2tf(f0 - __uint_as_float(bh[tn][0]));
                bh[tn][1] = f2tf(f1); bl[tn][1] = f2tf(f1 - __uint_as_float(bh[tn][1]));
            }
            #pragma unroll
            for (int tm = 0; tm < 2; tm++)
                #pragma unroll
                for (int tn = 0; tn < 4; tn++) {
                    mma8(acc[tm][tn], ah[tm][0],ah[tm][1],ah[tm][2],ah[tm][3], bh[tn][0],bh[tn][1]);
                    mma8(acc[tm][tn], al[tm][0],al[tm][1],al[tm][2],al[tm][3], bh[tn][0],bh[tn][1]);
                    mma8(acc[tm][tn], ah[tm][0],ah[tm][1],ah[tm][2],ah[tm][3], bl[tn][0],bl[tn][1]);
                }
        }
        __syncthreads();
    }
    #pragma unroll
    for (int tm = 0; tm < 2; tm++)
        #pragma unroll
        for (int tn = 0; tn < 4; tn++) {
            int row = i0 + wm0 + tm*16 + g;
            int col = wn0 + tn*8 + tg*2;
            *(float2*)(cb + (size_t)row*HDIM + col) =
                make_float2(acc[tm][tn][0], acc[tm][tn][1]);
            *(float2*)(cb + (size_t)(row+8)*HDIM + col) =
                make_float2(acc[tm][tn][2], acc[tm][tn][3]);
        }
}

// ---------------- plain layernorm over HDIM ----------------
__global__ __launch_bounds__(256) void ln_kernel(
    const float* __restrict__ x, const float* __restrict__ g,
    const float* __restrict__ b, float* __restrict__ out)
{
    int row = blockIdx.x;
    __shared__ float red[32];
    int tid = threadIdx.x;
    float v0 = x[(size_t)row*HDIM + tid];
    float v1 = x[(size_t)row*HDIM + tid + 256];
    float sum = blockReduceSum(v0 + v1, red);
    float m = sum * (1.0f / HDIM);
    float d0 = v0 - m, d1 = v1 - m;
    float ssq = blockReduceSum(d0*d0 + d1*d1, red);
    float rstd = rsqrtf(ssq * (1.0f / HDIM) + 1e-5f);
    out[(size_t)row*HDIM + tid      ] = d0 * rstd * g[tid]       + b[tid];
    out[(size_t)row*HDIM + tid + 256] = d1 * rstd * g[tid + 256] + b[tid + 256];
}

// ---------------- final projection: out = h[:, :, 1] @ Wp + bp ----------------
__global__ __launch_bounds__(256) void final_kernel(
    const float* __restrict__ h, const float* __restrict__ Wp,
    const float* __restrict__ bp, float* __restrict__ out)
{
    int bt = blockIdx.x;                 // b*T + t
    int b = bt / TT, t = bt % TT;
    const float* row = h + ((size_t)b*SS + 3*t + 1) * HDIM;
    __shared__ float sRow[HDIM];
    __shared__ float part[8][ADIM];
    int tid = threadIdx.x;
    sRow[tid] = row[tid];
    sRow[tid + 256] = row[tid + 256];
    __syncthreads();
    int c = tid & 31, g = tid >> 5;
    float a = 0.f;
    for (int k = g*64; k < (g+1)*64; k++) a = fmaf(sRow[k], Wp[(size_t)k*ADIM + c], a);
    part[g][c] = a;
    __syncthreads();
    if (tid < ADIM) {
        float s = bp[tid];
        #pragma unroll
        for (int g2 = 0; g2 < 8; g2++) s += part[g2][tid];
        out[(size_t)bt*ADIM + tid] = s;
    }
}

// ---------------- driver ----------------
extern "C" void kernel_launch(void* const* d_in, const int* in_sizes, int n_in,
                              void* d_out, int out_size)
{
    const int*   timesteps = (const int*)  d_in[0];
    const float* state_0   = (const float*)d_in[1];
    const float* state_1   = (const float*)d_in[2];
    const float* actions   = (const float*)d_in[3];
    const float* time_emb  = (const float*)d_in[4];
    const float* Ws  = (const float*)d_in[5];
    const float* bs  = (const float*)d_in[6];
    const float* Wa  = (const float*)d_in[7];
    const float* ba  = (const float*)d_in[8];
    const float* Wq  = (const float*)d_in[9];
    const float* bq  = (const float*)d_in[10];
    const float* Wk  = (const float*)d_in[11];
    const float* bk  = (const float*)d_in[12];
    const float* Wv  = (const float*)d_in[13];
    const float* bv  = (const float*)d_in[14];
    const float* Wo  = (const float*)d_in[15];
    const float* bo  = (const float*)d_in[16];
    const float* W1  = (const float*)d_in[17];
    const float* b1  = (const float*)d_in[18];
    const float* W2  = (const float*)d_in[19];
    const float* b2  = (const float*)d_in[20];
    const float* ln1_g = (const float*)d_in[21];
    const float* ln1_b = (const float*)d_in[22];
    const float* ln2_g = (const float*)d_in[23];
    const float* ln2_b = (const float*)d_in[24];
    const float* eln_g = (const float*)d_in[25];
    const float* eln_b = (const float*)d_in[26];
    const float* Wp  = (const float*)d_in[27];
    const float* bp  = (const float*)d_in[28];

    float *h, *q, *k, *v, *ctx, *xa, *ln1o, *pre2, *mlp, *sc;
    cudaGetSymbolAddress((void**)&h,    g_h);
    cudaGetSymbolAddress((void**)&q,    g_q);
    cudaGetSymbolAddress((void**)&k,    g_k);
    cudaGetSymbolAddress((void**)&v,    g_v);
    cudaGetSymbolAddress((void**)&ctx,  g_ctx);
    cudaGetSymbolAddress((void**)&xa,   g_xa);
    cudaGetSymbolAddress((void**)&ln1o, g_ln1);
    cudaGetSymbolAddress((void**)&pre2, g_pre2);
    cudaGetSymbolAddress((void**)&mlp,  g_mlp);
    cudaGetSymbolAddress((void**)&sc,   g_sc);

    embed_kernel<<<BB*SS, 256>>>(timesteps, state_0, state_1, actions, time_emb,
                                 Ws, bs, Wa, ba, eln_g, eln_b, h);

    dim3 gQKV(HDIM/128, MROWS/128, 3);   // (4, 48, 3)
    dim3 gH  (HDIM/128, MROWS/128);      // (4, 48)
    dim3 gF  (DFF /128, MROWS/128);      // (16, 48)
    dim3 gS  (SS/128, SS/128, BB*NH);    // (12, 12, 32)
    dim3 gC  (SS/128, BB*NH);            // (12, 32)

    for (int blk = 0; blk < NBLK; blk++) {
        const float* Wq_ = Wq + (size_t)blk*HDIM*HDIM;
        const float* Wk_ = Wk + (size_t)blk*HDIM*HDIM;
        const float* Wv_ = Wv + (size_t)blk*HDIM*HDIM;
        const float* Wo_ = Wo + (size_t)blk*HDIM*HDIM;
        const float* W1_ = W1 + (size_t)blk*HDIM*DFF;
        const float* W2_ = W2 + (size_t)blk*DFF*HDIM;
        const float* bq_ = bq + (size_t)blk*HDIM;
        const float* bk_ = bk + (size_t)blk*HDIM;
        const float* bv_ = bv + (size_t)blk*HDIM;
        const float* bo_ = bo + (size_t)blk*HDIM;
        const float* b1_ = b1 + (size_t)blk*DFF;
        const float* b2_ = b2 + (size_t)blk*HDIM;
        const float* g1_ = ln1_g + (size_t)blk*HDIM;
        const float* e1_ = ln1_b + (size_t)blk*HDIM;
        const float* g2_ = ln2_g + (size_t)blk*HDIM;
        const float* e2_ = ln2_b + (size_t)blk*HDIM;

        qkv_kernel<<<gQKV, 256>>>(h, Wq_, Wk_, Wv_, bq_, bk_, bv_, q, k, v);

        tscores_kernel<<<gS, 256>>>(q, k, sc);
        softmax_kernel<<<BB*NH*SS, 256>>>(sc);
        tctx_kernel   <<<gC, 256>>>(sc, v, ctx);

        tgemm_kernel<<<gH, 256>>>(ctx, Wo_, bo_, h, xa, MROWS, HDIM, HDIM, EP_BIAS_RES);
        ln_kernel   <<<MROWS, 256>>>(xa, g1_, e1_, ln1o);
        tgemm_kernel<<<gF, 256>>>(ln1o, W1_, b1_, nullptr, mlp, MROWS, DFF, HDIM, EP_BIAS_GELU);
        tgemm_kernel<<<gH, 256>>>(mlp, W2_, b2_, ln1o, pre2, MROWS, HDIM, DFF, EP_BIAS_RES);
        ln_kernel   <<<MROWS, 256>>>(pre2, g2_, e2_, h);
    }

    final_kernel<<<BB*TT, 256>>>(h, Wp, bp, (float*)d_out);
}

// round 3
// speedup vs baseline: 1.4198x; 1.4198x over previous
#include <cuda_runtime.h>
#include <math.h>

#define BB 4
#define TT 512
#define SS 1536           // S = 3*T
#define SDIM 64
#define ADIM 32
#define HDIM 512
#define NH 8
#define DH 64
#define NBLK 6
#define DFF 2048
#define MROWS (BB*SS)     // 6144

enum { EP_BIAS = 0, EP_BIAS_RES = 1, EP_BIAS_GELU = 2 };

// ---------------- scratch (static device globals; no runtime allocs) ----------
__device__ float g_h   [MROWS * HDIM];
__device__ float g_q   [MROWS * HDIM];
__device__ float g_k   [MROWS * HDIM];
__device__ float g_v   [MROWS * HDIM];
__device__ float g_ctx [MROWS * HDIM];
__device__ float g_xa  [MROWS * HDIM];
__device__ float g_ln1 [MROWS * HDIM];
__device__ float g_pre2[MROWS * HDIM];
__device__ float g_mlp [MROWS * DFF];
__device__ float g_sc  [(size_t)BB * NH * SS * SS];   // 302 MB scores

// ---------------- tf32 helpers ----------------
__device__ __forceinline__ unsigned f2tf(float x) {
    unsigned r; asm("cvt.rna.tf32.f32 %0, %1;" : "=r"(r) : "f"(x)); return r;
}
// split fp32 into tf32 hi + tf32 lo (x ~= hi + lo to ~19 mantissa bits)
__device__ __forceinline__ uint2 split2(float x) {
    unsigned hi = f2tf(x);
    unsigned lo = f2tf(x - __uint_as_float(hi));
    return make_uint2(hi, lo);
}
__device__ __forceinline__ void mma8(float c[4],
    unsigned a0, unsigned a1, unsigned a2, unsigned a3,
    unsigned b0, unsigned b1)
{
    asm volatile(
      "mma.sync.aligned.m16n8k8.row.col.f32.tf32.tf32.f32 "
      "{%0,%1,%2,%3},{%4,%5,%6,%7},{%8,%9},{%0,%1,%2,%3};"
      : "+f"(c[0]), "+f"(c[1]), "+f"(c[2]), "+f"(c[3])
      : "r"(a0), "r"(a1), "r"(a2), "r"(a3), "r"(b0), "r"(b1));
}

// ---------------- reductions ----------------
__device__ __forceinline__ float blockReduceSum(float v, float* sm) {
    int lane = threadIdx.x & 31, wid = threadIdx.x >> 5;
    #pragma unroll
    for (int o = 16; o; o >>= 1) v += __shfl_down_sync(0xffffffffu, v, o);
    if (lane == 0) sm[wid] = v;
    __syncthreads();
    float r = 0.f;
    if (wid == 0) {
        r = (lane < 8) ? sm[lane] : 0.f;
        #pragma unroll
        for (int o = 4; o; o >>= 1) r += __shfl_down_sync(0xffffffffu, r, o);
        if (lane == 0) sm[0] = r;
    }
    __syncthreads();
    r = sm[0];
    __syncthreads();
    return r;
}

__device__ __forceinline__ float blockReduceMax(float v, float* sm) {
    int lane = threadIdx.x & 31, wid = threadIdx.x >> 5;
    #pragma unroll
    for (int o = 16; o; o >>= 1) v = fmaxf(v, __shfl_down_sync(0xffffffffu, v, o));
    if (lane == 0) sm[wid] = v;
    __syncthreads();
    float r = -1e30f;
    if (wid == 0) {
        r = (lane < 8) ? sm[lane] : -1e30f;
        #pragma unroll
        for (int o = 4; o; o >>= 1) r = fmaxf(r, __shfl_down_sync(0xffffffffu, r, o));
        if (lane == 0) sm[0] = r;
    }
    __syncthreads();
    r = sm[0];
    __syncthreads();
    return r;
}

// ---------------- embedding + eLN (one block per sequence row) ----------------
__global__ __launch_bounds__(256) void embed_kernel(
    const int* __restrict__ timesteps, const float* __restrict__ s0,
    const float* __restrict__ s1, const float* __restrict__ act,
    const float* __restrict__ temb,
    const float* __restrict__ Ws, const float* __restrict__ bs,
    const float* __restrict__ Wa, const float* __restrict__ ba,
    const float* __restrict__ eg, const float* __restrict__ eb,
    float* __restrict__ out)
{
    int s = blockIdx.x;
    int b = s / SS, sr = s % SS;
    int t = sr / 3, r = sr % 3;

    __shared__ float sIn[SDIM];
    __shared__ float red[32];

    const float* inp; const float* W; const float* bias; int Kin;
    if (r == 0)      { inp = s0  + (size_t)(b*TT + t)*SDIM; W = Ws; bias = bs; Kin = SDIM; }
    else if (r == 1) { inp = s1  + (size_t)(b*TT + t)*SDIM; W = Ws; bias = bs; Kin = SDIM; }
    else             { inp = act + (size_t)(b*TT + t)*ADIM; W = Wa; bias = ba; Kin = ADIM; }

    int tid = threadIdx.x;
    if (tid < Kin) sIn[tid] = inp[tid];
    __syncthreads();

    int tsv = timesteps[b*TT + t];
    const float* te = temb + (size_t)tsv * HDIM;

    float v0, v1;
    {
        int c = tid;
        float a = bias[c] + te[c];
        for (int k = 0; k < Kin; k++) a = fmaf(sIn[k], W[(size_t)k*HDIM + c], a);
        v0 = a;
        c = tid + 256;
        a = bias[c] + te[c];
        for (int k = 0; k < Kin; k++) a = fmaf(sIn[k], W[(size_t)k*HDIM + c], a);
        v1 = a;
    }
    float sum = blockReduceSum(v0 + v1, red);
    float m = sum * (1.0f / HDIM);
    float d0 = v0 - m, d1 = v1 - m;
    float ssq = blockReduceSum(d0*d0 + d1*d1, red);
    float rstd = rsqrtf(ssq * (1.0f / HDIM) + 1e-5f);
    out[(size_t)s*HDIM + tid      ] = d0 * rstd * eg[tid]       + eb[tid];
    out[(size_t)s*HDIM + tid + 256] = d1 * rstd * eg[tid + 256] + eb[tid + 256];
}

// ============ tensor-core GEMM: C[M,N] = A[M,K] @ B[K,N] (3xTF32) ==============
// 256 threads, tile 128x128, BK=16. Warp grid 2(m) x 4(n): warp tile 64x32.
// Shared tiles hold pre-split (hi, lo) tf32 pairs -> inner loop is LDS.64 + mma.
__device__ __forceinline__ void tgemm_body(
    const float* __restrict__ A, const float* __restrict__ B,
    const float* __restrict__ bias, const float* __restrict__ res,
    float* __restrict__ C, int M, int N, int K, int ep)
{
    __shared__ uint2 As2[16][136];
    __shared__ uint2 Bs2[16][136];
    const int tid  = threadIdx.x, lane = tid & 31, warp = tid >> 5;
    const int g    = lane >> 2,  tg   = lane & 3;
    const int wm0  = (warp >> 2) * 64, wn0 = (warp & 3) * 32;
    const int m0   = blockIdx.y * 128, n0 = blockIdx.x * 128;
    const int ar   = tid >> 2,  ac = (tid & 3) * 4;
    const int brr  = tid >> 5,  bcc = (tid & 31) * 4;

    float acc[4][4][4];
    #pragma unroll
    for (int i = 0; i < 4; i++)
        #pragma unroll
        for (int j = 0; j < 4; j++)
            #pragma unroll
            for (int l = 0; l < 4; l++) acc[i][j][l] = 0.f;

    for (int k0 = 0; k0 < K; k0 += 16) {
        float4 av0 = *(const float4*)(A + (size_t)(m0 + ar)*K      + k0 + ac);
        float4 av1 = *(const float4*)(A + (size_t)(m0 + ar + 64)*K + k0 + ac);
        float4 bv0 = *(const float4*)(B + (size_t)(k0 + brr)*N     + n0 + bcc);
        float4 bv1 = *(const float4*)(B + (size_t)(k0 + brr + 8)*N + n0 + bcc);
        As2[ac+0][ar] = split2(av0.x); As2[ac+1][ar] = split2(av0.y);
        As2[ac+2][ar] = split2(av0.z); As2[ac+3][ar] = split2(av0.w);
        As2[ac+0][ar+64] = split2(av1.x); As2[ac+1][ar+64] = split2(av1.y);
        As2[ac+2][ar+64] = split2(av1.z); As2[ac+3][ar+64] = split2(av1.w);
        Bs2[brr][bcc+0] = split2(bv0.x); Bs2[brr][bcc+1] = split2(bv0.y);
        Bs2[brr][bcc+2] = split2(bv0.z); Bs2[brr][bcc+3] = split2(bv0.w);
        Bs2[brr+8][bcc+0] = split2(bv1.x); Bs2[brr+8][bcc+1] = split2(bv1.y);
        Bs2[brr+8][bcc+2] = split2(bv1.z); Bs2[brr+8][bcc+3] = split2(bv1.w);
        __syncthreads();
        #pragma unroll
        for (int ks = 0; ks < 16; ks += 8) {
            uint2 bf[4][2];
            #pragma unroll
            for (int tn = 0; tn < 4; tn++) {
                int n = wn0 + tn*8 + g;
                bf[tn][0] = Bs2[ks+tg][n];
                bf[tn][1] = Bs2[ks+tg+4][n];
            }
            #pragma unroll
            for (int tm = 0; tm < 4; tm++) {
                int m = wm0 + tm*16 + g;
                uint2 a0 = As2[ks+tg][m],   a1 = As2[ks+tg][m+8];
                uint2 a2 = As2[ks+tg+4][m], a3 = As2[ks+tg+4][m+8];
                #pragma unroll
                for (int tn = 0; tn < 4; tn++) {
                    mma8(acc[tm][tn], a0.x,a1.x,a2.x,a3.x, bf[tn][0].x, bf[tn][1].x);
                    mma8(acc[tm][tn], a0.y,a1.y,a2.y,a3.y, bf[tn][0].x, bf[tn][1].x);
                    mma8(acc[tm][tn], a0.x,a1.x,a2.x,a3.x, bf[tn][0].y, bf[tn][1].y);
                }
            }
        }
        __syncthreads();
    }
    #pragma unroll
    for (int tm = 0; tm < 4; tm++) {
        #pragma unroll
        for (int tn = 0; tn < 4; tn++) {
            int row = m0 + wm0 + tm*16 + g;
            int col = n0 + wn0 + tn*8 + tg*2;
            float b0v = bias[col], b1v = bias[col+1];
            float v00 = acc[tm][tn][0] + b0v, v01 = acc[tm][tn][1] + b1v;
            float v10 = acc[tm][tn][2] + b0v, v11 = acc[tm][tn][3] + b1v;
            if (ep == EP_BIAS_RES) {
                v00 += res[(size_t)row*N + col];     v01 += res[(size_t)row*N + col + 1];
                v10 += res[(size_t)(row+8)*N + col]; v11 += res[(size_t)(row+8)*N + col + 1];
            } else if (ep == EP_BIAS_GELU) {
                v00 = 0.5f*v00*(1.0f + erff(v00*0.70710678118654752f));
                v01 = 0.5f*v01*(1.0f + erff(v01*0.70710678118654752f));
                v10 = 0.5f*v10*(1.0f + erff(v10*0.70710678118654752f));
                v11 = 0.5f*v11*(1.0f + erff(v11*0.70710678118654752f));
            }
            *(float2*)(C + (size_t)row*N + col)     = make_float2(v00, v01);
            *(float2*)(C + (size_t)(row+8)*N + col) = make_float2(v10, v11);
        }
    }
}

__global__ __launch_bounds__(256) void tgemm_kernel(
    const float* __restrict__ A, const float* __restrict__ B,
    const float* __restrict__ bias, const float* __restrict__ res,
    float* __restrict__ C, int M, int N, int K, int ep)
{
    tgemm_body(A, B, bias, res, C, M, N, K, ep);
}

// fused QKV: blockIdx.z selects the projection
__global__ __launch_bounds__(256) void qkv_kernel(
    const float* __restrict__ h,
    const float* __restrict__ Wq, const float* __restrict__ Wk, const float* __restrict__ Wv,
    const float* __restrict__ bq, const float* __restrict__ bk, const float* __restrict__ bv,
    float* __restrict__ q, float* __restrict__ k, float* __restrict__ v)
{
    const float* W; const float* bias; float* out;
    if      (blockIdx.z == 0) { W = Wq; bias = bq; out = q; }
    else if (blockIdx.z == 1) { W = Wk; bias = bk; out = k; }
    else                      { W = Wv; bias = bv; out = v; }
    tgemm_body(h, W, bias, nullptr, out, MROWS, HDIM, HDIM, EP_BIAS);
}

// ---------- scores = Q @ K^T (NT), lower-triangle 128x128 tiles, 3xTF32 -------
__global__ __launch_bounds__(256) void tscores_kernel(
    const float* __restrict__ q, const float* __restrict__ k, float* __restrict__ sc)
{
    int jt = blockIdx.x, it = blockIdx.y;
    if (jt > it) return;
    int bh = blockIdx.z, b = bh >> 3, h = bh & 7;
    const float* qb = q + (size_t)b*SS*HDIM + h*DH;
    const float* kb = k + (size_t)b*SS*HDIM + h*DH;
    float* cb = sc + (size_t)bh * SS * SS;
    int i0 = it * 128, j0 = jt * 128;

    __shared__ uint2 Qs2[16][136];
    __shared__ uint2 Ks2[128][20];
    const int tid  = threadIdx.x, lane = tid & 31, warp = tid >> 5;
    const int g    = lane >> 2,  tg   = lane & 3;
    const int wm0  = (warp >> 2) * 64, wn0 = (warp & 3) * 32;
    const int ar   = tid >> 2,  ac = (tid & 3) * 4;

    float acc[4][4][4];
    #pragma unroll
    for (int i = 0; i < 4; i++)
        #pragma unroll
        for (int j = 0; j < 4; j++)
            #pragma unroll
            for (int l = 0; l < 4; l++) acc[i][j][l] = 0.f;

    for (int k0 = 0; k0 < DH; k0 += 16) {
        float4 q0 = *(const float4*)(qb + (size_t)(i0 + ar)*HDIM      + k0 + ac);
        float4 q1 = *(const float4*)(qb + (size_t)(i0 + ar + 64)*HDIM + k0 + ac);
        float4 k0v = *(const float4*)(kb + (size_t)(j0 + ar)*HDIM      + k0 + ac);
        float4 k1v = *(const float4*)(kb + (size_t)(j0 + ar + 64)*HDIM + k0 + ac);
        Qs2[ac+0][ar] = split2(q0.x); Qs2[ac+1][ar] = split2(q0.y);
        Qs2[ac+2][ar] = split2(q0.z); Qs2[ac+3][ar] = split2(q0.w);
        Qs2[ac+0][ar+64] = split2(q1.x); Qs2[ac+1][ar+64] = split2(q1.y);
        Qs2[ac+2][ar+64] = split2(q1.z); Qs2[ac+3][ar+64] = split2(q1.w);
        Ks2[ar][ac+0] = split2(k0v.x); Ks2[ar][ac+1] = split2(k0v.y);
        Ks2[ar][ac+2] = split2(k0v.z); Ks2[ar][ac+3] = split2(k0v.w);
        Ks2[ar+64][ac+0] = split2(k1v.x); Ks2[ar+64][ac+1] = split2(k1v.y);
        Ks2[ar+64][ac+2] = split2(k1v.z); Ks2[ar+64][ac+3] = split2(k1v.w);
        __syncthreads();
        #pragma unroll
        for (int ks = 0; ks < 16; ks += 8) {
            uint2 bf[4][2];
            #pragma unroll
            for (int tn = 0; tn < 4; tn++) {
                int n = wn0 + tn*8 + g;
                bf[tn][0] = Ks2[n][ks+tg];
                bf[tn][1] = Ks2[n][ks+tg+4];
            }
            #pragma unroll
            for (int tm = 0; tm < 4; tm++) {
                int m = wm0 + tm*16 + g;
                uint2 a0 = Qs2[ks+tg][m],   a1 = Qs2[ks+tg][m+8];
                uint2 a2 = Qs2[ks+tg+4][m], a3 = Qs2[ks+tg+4][m+8];
                #pragma unroll
                for (int tn = 0; tn < 4; tn++) {
                    mma8(acc[tm][tn], a0.x,a1.x,a2.x,a3.x, bf[tn][0].x, bf[tn][1].x);
                    mma8(acc[tm][tn], a0.y,a1.y,a2.y,a3.y, bf[tn][0].x, bf[tn][1].x);
                    mma8(acc[tm][tn], a0.x,a1.x,a2.x,a3.x, bf[tn][0].y, bf[tn][1].y);
                }
            }
        }
        __syncthreads();
    }
    const float scale = 0.125f;
    #pragma unroll
    for (int tm = 0; tm < 4; tm++)
        #pragma unroll
        for (int tn = 0; tn < 4; tn++) {
            int row = i0 + wm0 + tm*16 + g;
            int col = j0 + wn0 + tn*8 + tg*2;
            *(float2*)(cb + (size_t)row*SS + col) =
                make_float2(acc[tm][tn][0]*scale, acc[tm][tn][1]*scale);
            *(float2*)(cb + (size_t)(row+8)*SS + col) =
                make_float2(acc[tm][tn][2]*scale, acc[tm][tn][3]*scale);
        }
}

// ------------- causal row softmax, vectorized single read/write ---------------
__global__ __launch_bounds__(256) void softmax_kernel(float* __restrict__ sc)
{
    size_t rid = blockIdx.x;            // bh*S + i
    int i = (int)(rid % SS);
    float* row = sc + rid * (size_t)SS;
    int n = i + 1;
    int nf = (n + 3) >> 2;              // float4 count covering valid region
    int endf = (((i >> 7) + 1) << 7) >> 2;  // 128-tile boundary in float4 units
    __shared__ float red[32];
    int tid = threadIdx.x;

    float4 vals[2];
    int cnt = 0;
    float mx = -1e30f;
    for (int f = tid; f < nf; f += 256) {
        float4 x = *(const float4*)(row + 4*(size_t)f);
        int b4 = 4*f;
        if (b4 + 1 >= n) x.y = -1e30f;
        if (b4 + 2 >= n) x.z = -1e30f;
        if (b4 + 3 >= n) x.w = -1e30f;
        vals[cnt++] = x;
        mx = fmaxf(fmaxf(mx, fmaxf(x.x, x.y)), fmaxf(x.z, x.w));
    }
    mx = blockReduceMax(mx, red);

    float sum = 0.f;
    #pragma unroll
    for (int l = 0; l < 2; l++)
        if (l < cnt) {
            float4& x = vals[l];
            x.x = __expf(x.x - mx); x.y = __expf(x.y - mx);
            x.z = __expf(x.z - mx); x.w = __expf(x.w - mx);
            sum += (x.x + x.y) + (x.z + x.w);
        }
    sum = blockReduceSum(sum, red);
    float inv = 1.0f / sum;

    cnt = 0;
    for (int f = tid; f < nf; f += 256) {
        float4 x = vals[cnt++];
        x.x *= inv; x.y *= inv; x.z *= inv; x.w *= inv;
        *(float4*)(row + 4*(size_t)f) = x;
    }
    for (int f = nf + tid; f < endf; f += 256)
        *(float4*)(row + 4*(size_t)f) = make_float4(0.f, 0.f, 0.f, 0.f);
}

// ---------- ctx = attn @ V (NN), tile 128x64, causal K-limit, 3xTF32 ----------
__global__ __launch_bounds__(256) void tctx_kernel(
    const float* __restrict__ at, const float* __restrict__ v, float* __restrict__ ctx)
{
    int it = blockIdx.x, bh = blockIdx.y, b = bh >> 3, h = bh & 7;
    const float* ab = at + (size_t)bh * SS * SS;
    const float* vb = v   + (size_t)b*SS*HDIM + h*DH;
    float* cb       = ctx + (size_t)b*SS*HDIM + h*DH;
    int i0 = it * 128;
    int kmax = (it + 1) * 128;

    __shared__ uint2 As2[16][136];
    __shared__ uint2 Bs2[16][72];
    const int tid  = threadIdx.x, lane = tid & 31, warp = tid >> 5;
    const int g    = lane >> 2,  tg   = lane & 3;
    const int wm0  = (warp >> 1) * 32, wn0 = (warp & 1) * 32;
    const int ar   = tid >> 2,  ac = (tid & 3) * 4;
    const int brr  = tid >> 4,  bcc = (tid & 15) * 4;

    float acc[2][4][4];
    #pragma unroll
    for (int i = 0; i < 2; i++)
        #pragma unroll
        for (int j = 0; j < 4; j++)
            #pragma unroll
            for (int l = 0; l < 4; l++) acc[i][j][l] = 0.f;

    for (int k0 = 0; k0 < kmax; k0 += 16) {
        float4 a0 = *(const float4*)(ab + (size_t)(i0 + ar)*SS      + k0 + ac);
        float4 a1 = *(const float4*)(ab + (size_t)(i0 + ar + 64)*SS + k0 + ac);
        float4 b0 = *(const float4*)(vb + (size_t)(k0 + brr)*HDIM + bcc);
        As2[ac+0][ar] = split2(a0.x); As2[ac+1][ar] = split2(a0.y);
        As2[ac+2][ar] = split2(a0.z); As2[ac+3][ar] = split2(a0.w);
        As2[ac+0][ar+64] = split2(a1.x); As2[ac+1][ar+64] = split2(a1.y);
        As2[ac+2][ar+64] = split2(a1.z); As2[ac+3][ar+64] = split2(a1.w);
        Bs2[brr][bcc+0] = split2(b0.x); Bs2[brr][bcc+1] = split2(b0.y);
        Bs2[brr][bcc+2] = split2(b0.z); Bs2[brr][bcc+3] = split2(b0.w);
        __syncthreads();
        #pragma unroll
        for (int ks = 0; ks < 16; ks += 8) {
            uint2 bf[4][2];
            #pragma unroll
            for (int tn = 0; tn < 4; tn++) {
                int n = wn0 + tn*8 + g;
                bf[tn][0] = Bs2[ks+tg][n];
                bf[tn][1] = Bs2[ks+tg+4][n];
            }
            #pragma unroll
            for (int tm = 0; tm < 2; tm++) {
                int m = wm0 + tm*16 + g;
                uint2 a0f = As2[ks+tg][m],   a1f = As2[ks+tg][m+8];
                uint2 a2f = As2[ks+tg+4][m], a3f = As2[ks+tg+4][m+8];
                #pragma unroll
                for (int tn = 0; tn < 4; tn++) {
                    mma8(acc[tm][tn], a0f.x,a1f.x,a2f.x,a3f.x, bf[tn][0].x, bf[tn][1].x);
                    mma8(acc[tm][tn], a0f.y,a1f.y,a2f.y,a3f.y, bf[tn][0].x, bf[tn][1].x);
                    mma8(acc[tm][tn], a0f.x,a1f.x,a2f.x,a3f.x, bf[tn][0].y, bf[tn][1].y);
                }
            }
        }
        __syncthreads();
    }
    #pragma unroll
    for (int tm = 0; tm < 2; tm++)
        #pragma unroll
        for (int tn = 0; tn < 4; tn++) {
            int row = i0 + wm0 + tm*16 + g;
            int col = wn0 + tn*8 + tg*2;
            *(float2*)(cb + (size_t)row*HDIM + col) =
                make_float2(acc[tm][tn][0], acc[tm][tn][1]);
            *(float2*)(cb + (size_t)(row+8)*HDIM + col) =
                make_float2(acc[tm][tn][2], acc[tm][tn][3]);
        }
}

// ---------------- plain layernorm over HDIM ----------------
__global__ __launch_bounds__(256) void ln_kernel(
    const float* __restrict__ x, const float* __restrict__ g,
    const float* __restrict__ b, float* __restrict__ out)
{
    int row = blockIdx.x;
    __shared__ float red[32];
    int tid = threadIdx.x;
    float v0 = x[(size_t)row*HDIM + tid];
    float v1 = x[(size_t)row*HDIM + tid + 256];
    float sum = blockReduceSum(v0 + v1, red);
    float m = sum * (1.0f / HDIM);
    float d0 = v0 - m, d1 = v1 - m;
    float ssq = blockReduceSum(d0*d0 + d1*d1, red);
    float rstd = rsqrtf(ssq * (1.0f / HDIM) + 1e-5f);
    out[(size_t)row*HDIM + tid      ] = d0 * rstd * g[tid]       + b[tid];
    out[(size_t)row*HDIM + tid + 256] = d1 * rstd * g[tid + 256] + b[tid + 256];
}

// ---------------- final projection: out = h[:, :, 1] @ Wp + bp ----------------
__global__ __launch_bounds__(256) void final_kernel(
    const float* __restrict__ h, const float* __restrict__ Wp,
    const float* __restrict__ bp, float* __restrict__ out)
{
    int bt = blockIdx.x;                 // b*T + t
    int b = bt / TT, t = bt % TT;
    const float* row = h + ((size_t)b*SS + 3*t + 1) * HDIM;
    __shared__ float sRow[HDIM];
    __shared__ float part[8][ADIM];
    int tid = threadIdx.x;
    sRow[tid] = row[tid];
    sRow[tid + 256] = row[tid + 256];
    __syncthreads();
    int c = tid & 31, g = tid >> 5;
    float a = 0.f;
    for (int k = g*64; k < (g+1)*64; k++) a = fmaf(sRow[k], Wp[(size_t)k*ADIM + c], a);
    part[g][c] = a;
    __syncthreads();
    if (tid < ADIM) {
        float s = bp[tid];
        #pragma unroll
        for (int g2 = 0; g2 < 8; g2++) s += part[g2][tid];
        out[(size_t)bt*ADIM + tid] = s;
    }
}

// ---------------- driver ----------------
extern "C" void kernel_launch(void* const* d_in, const int* in_sizes, int n_in,
                              void* d_out, int out_size)
{
    const int*   timesteps = (const int*)  d_in[0];
    const float* state_0   = (const float*)d_in[1];
    const float* state_1   = (const float*)d_in[2];
    const float* actions   = (const float*)d_in[3];
    const float* time_emb  = (const float*)d_in[4];
    const float* Ws  = (const float*)d_in[5];
    const float* bs  = (const float*)d_in[6];
    const float* Wa  = (const float*)d_in[7];
    const float* ba  = (const float*)d_in[8];
    const float* Wq  = (const float*)d_in[9];
    const float* bq  = (const float*)d_in[10];
    const float* Wk  = (const float*)d_in[11];
    const float* bk  = (const float*)d_in[12];
    const float* Wv  = (const float*)d_in[13];
    const float* bv  = (const float*)d_in[14];
    const float* Wo  = (const float*)d_in[15];
    const float* bo  = (const float*)d_in[16];
    const float* W1  = (const float*)d_in[17];
    const float* b1  = (const float*)d_in[18];
    const float* W2  = (const float*)d_in[19];
    const float* b2  = (const float*)d_in[20];
    const float* ln1_g = (const float*)d_in[21];
    const float* ln1_b = (const float*)d_in[22];
    const float* ln2_g = (const float*)d_in[23];
    const float* ln2_b = (const float*)d_in[24];
    const float* eln_g = (const float*)d_in[25];
    const float* eln_b = (const float*)d_in[26];
    const float* Wp  = (const float*)d_in[27];
    const float* bp  = (const float*)d_in[28];

    float *h, *q, *k, *v, *ctx, *xa, *ln1o, *pre2, *mlp, *sc;
    cudaGetSymbolAddress((void**)&h,    g_h);
    cudaGetSymbolAddress((void**)&q,    g_q);
    cudaGetSymbolAddress((void**)&k,    g_k);
    cudaGetSymbolAddress((void**)&v,    g_v);
    cudaGetSymbolAddress((void**)&ctx,  g_ctx);
    cudaGetSymbolAddress((void**)&xa,   g_xa);
    cudaGetSymbolAddress((void**)&ln1o, g_ln1);
    cudaGetSymbolAddress((void**)&pre2, g_pre2);
    cudaGetSymbolAddress((void**)&mlp,  g_mlp);
    cudaGetSymbolAddress((void**)&sc,   g_sc);

    embed_kernel<<<BB*SS, 256>>>(timesteps, state_0, state_1, actions, time_emb,
                                 Ws, bs, Wa, ba, eln_g, eln_b, h);

    dim3 gQKV(HDIM/128, MROWS/128, 3);   // (4, 48, 3)
    dim3 gH  (HDIM/128, MROWS/128);      // (4, 48)
    dim3 gF  (DFF /128, MROWS/128);      // (16, 48)
    dim3 gS  (SS/128, SS/128, BB*NH);    // (12, 12, 32)
    dim3 gC  (SS/128, BB*NH);            // (12, 32)

    for (int blk = 0; blk < NBLK; blk++) {
        const float* Wq_ = Wq + (size_t)blk*HDIM*HDIM;
        const float* Wk_ = Wk + (size_t)blk*HDIM*HDIM;
        const float* Wv_ = Wv + (size_t)blk*HDIM*HDIM;
        const float* Wo_ = Wo + (size_t)blk*HDIM*HDIM;
        const float* W1_ = W1 + (size_t)blk*HDIM*DFF;
        const float* W2_ = W2 + (size_t)blk*DFF*HDIM;
        const float* bq_ = bq + (size_t)blk*HDIM;
        const float* bk_ = bk + (size_t)blk*HDIM;
        const float* bv_ = bv + (size_t)blk*HDIM;
        const float* bo_ = bo + (size_t)blk*HDIM;
        const float* b1_ = b1 + (size_t)blk*DFF;
        const float* b2_ = b2 + (size_t)blk*HDIM;
        const float* g1_ = ln1_g + (size_t)blk*HDIM;
        const float* e1_ = ln1_b + (size_t)blk*HDIM;
        const float* g2_ = ln2_g + (size_t)blk*HDIM;
        const float* e2_ = ln2_b + (size_t)blk*HDIM;

        qkv_kernel<<<gQKV, 256>>>(h, Wq_, Wk_, Wv_, bq_, bk_, bv_, q, k, v);

        tscores_kernel<<<gS, 256>>>(q, k, sc);
        softmax_kernel<<<BB*NH*SS, 256>>>(sc);
        tctx_kernel   <<<gC, 256>>>(sc, v, ctx);

        tgemm_kernel<<<gH, 256>>>(ctx, Wo_, bo_, h, xa, MROWS, HDIM, HDIM, EP_BIAS_RES);
        ln_kernel   <<<MROWS, 256>>>(xa, g1_, e1_, ln1o);
        tgemm_kernel<<<gF, 256>>>(ln1o, W1_, b1_, nullptr, mlp, MROWS, DFF, HDIM, EP_BIAS_GELU);
        tgemm_kernel<<<gH, 256>>>(mlp, W2_, b2_, ln1o, pre2, MROWS, HDIM, DFF, EP_BIAS_RES);
        ln_kernel   <<<MROWS, 256>>>(pre2, g2_, e2_, h);
    }

    final_kernel<<<BB*TT, 256>>>(h, Wp, bp, (float*)d_out);
}